// round 7
// baseline (speedup 1.0000x reference)
#include <cuda_runtime.h>
#include <cuda_bf16.h>
#include <cstdint>

#define B_DIM 64
#define H_DIM 512
#define I_DIM 512
#define T_DIM 512

// ---------------------------------------------------------------------------
// f32x2 helpers
// ---------------------------------------------------------------------------
__device__ __forceinline__ uint64_t pack2(float lo, float hi)
{
    uint64_t r;
    asm("mov.b64 %0, {%1, %2};" : "=l"(r)
        : "r"(__float_as_uint(lo)), "r"(__float_as_uint(hi)));
    return r;
}
__device__ __forceinline__ uint64_t fma2(uint64_t a, uint64_t b, uint64_t c)
{
    uint64_t d;
    asm("fma.rn.f32x2 %0, %1, %2, %3;" : "=l"(d) : "l"(a), "l"(b), "l"(c));
    return d;
}
__device__ __forceinline__ void unpack2(uint64_t v, float& lo, float& hi)
{
    uint32_t l, h;
    asm("mov.b64 {%0, %1}, %2;" : "=r"(l), "=r"(h) : "l"(v));
    lo = __uint_as_float(l); hi = __uint_as_float(h);
}
__device__ __forceinline__ void lds_v2b64(uint32_t addr, uint64_t& p, uint64_t& q)
{
    asm volatile("ld.shared.v2.b64 {%0, %1}, [%2];"
                 : "=l"(p), "=l"(q) : "r"(addr));
}

// ---------------------------------------------------------------------------
// Kernel 1: U[t,b,h] = sum_i X[b,i,t]*Wax[i,h] + bx[h] + ba[h]
// FFMA2 edition: accumulators paired over adjacent t-rows.
// ---------------------------------------------------------------------------
__global__ void __launch_bounds__(256)
precompute_kernel(const float* __restrict__ X,
                  const float* __restrict__ Wax,
                  const float* __restrict__ bx,
                  const float* __restrict__ ba,
                  float* __restrict__ U)
{
    __shared__ float As[16][64];   // [i-chunk][t]
    __shared__ float Bs[16][64];   // [i-chunk][h]

    const int b  = blockIdx.z;
    const int t0 = blockIdx.y * 64;
    const int h0 = blockIdx.x * 64;
    const int tid = threadIdx.x;
    const int tx = tid & 15;
    const int ty = tid >> 4;

    const float* Xb = X + (size_t)b * I_DIM * T_DIM;

    // acc2[p][c]: f32x2 over t-rows (2p, 2p+1) of this thread's 4x4 tile
    uint64_t acc2[2][4];
#pragma unroll
    for (int p = 0; p < 2; p++)
#pragma unroll
        for (int c = 0; c < 4; c++) acc2[p][c] = 0;

    const int lr = tid >> 4;
    const int lq = tid & 15;
    const uint32_t As_s = (uint32_t)__cvta_generic_to_shared(&As[0][0]);

    for (int i0 = 0; i0 < I_DIM; i0 += 16) {
        const float4* srcA = (const float4*)(Xb + (size_t)(i0 + lr) * T_DIM + t0);
        const float4* srcB = (const float4*)(Wax + (size_t)(i0 + lr) * H_DIM + h0);
        ((float4*)&As[lr][0])[lq] = srcA[lq];
        ((float4*)&Bs[lr][0])[lq] = srcB[lq];
        __syncthreads();
#pragma unroll
        for (int kk = 0; kk < 16; kk++) {
            uint64_t av01, av23;
            lds_v2b64(As_s + (uint32_t)(kk * 64 + ty * 4) * 4u, av01, av23);
            float4 bv = *(const float4*)&Bs[kk][tx * 4];
            uint64_t s;
            s = pack2(bv.x, bv.x);
            acc2[0][0] = fma2(av01, s, acc2[0][0]);
            acc2[1][0] = fma2(av23, s, acc2[1][0]);
            s = pack2(bv.y, bv.y);
            acc2[0][1] = fma2(av01, s, acc2[0][1]);
            acc2[1][1] = fma2(av23, s, acc2[1][1]);
            s = pack2(bv.z, bv.z);
            acc2[0][2] = fma2(av01, s, acc2[0][2]);
            acc2[1][2] = fma2(av23, s, acc2[1][2]);
            s = pack2(bv.w, bv.w);
            acc2[0][3] = fma2(av01, s, acc2[0][3]);
            acc2[1][3] = fma2(av23, s, acc2[1][3]);
        }
        __syncthreads();
    }

    float bias[4];
#pragma unroll
    for (int c = 0; c < 4; c++) {
        int h = h0 + tx * 4 + c;
        bias[c] = bx[h] + ba[h];
    }

    float acc[4][4];
#pragma unroll
    for (int c = 0; c < 4; c++) {
        unpack2(acc2[0][c], acc[0][c], acc[1][c]);
        unpack2(acc2[1][c], acc[2][c], acc[3][c]);
    }

#pragma unroll
    for (int r = 0; r < 4; r++) {
        int t = t0 + ty * 4 + r;
        float4 v;
        v.x = acc[r][0] + bias[0];
        v.y = acc[r][1] + bias[1];
        v.z = acc[r][2] + bias[2];
        v.w = acc[r][3] + bias[3];
        *(float4*)&U[(size_t)t * (B_DIM * H_DIM) + (size_t)b * H_DIM + h0 + tx * 4] = v;
    }
}

// tanh = 1 - 2/(e^{2x}+1) via ex2/rcp approx (~1e-6 rel err, saturates).
__device__ __forceinline__ float ftanh(float x)
{
    float e;
    asm("ex2.approx.f32 %0, %1;" : "=f"(e) : "f"(x * 2.885390081777927f));
    float r;
    asm("rcp.approx.f32 %0, %1;" : "=f"(r) : "f"(e + 1.0f));
    return fmaf(-2.0f, r, 1.0f);
}

__device__ __forceinline__ void mbar_wait(uint32_t mbar, uint32_t parity)
{
    uint32_t done;
    asm volatile(
        "{\n\t.reg .pred p;\n\t"
        "mbarrier.try_wait.parity.acquire.cta.shared::cta.b64 p, [%1], %2;\n\t"
        "selp.b32 %0, 1, 0, p;\n\t}"
        : "=r"(done) : "r"(mbar), "r"(parity) : "memory");
    if (!done) {
        asm volatile(
            "{\n\t.reg .pred P1;\n\t"
            "W_%=:\n\t"
            "mbarrier.try_wait.parity.acquire.cta.shared::cta.b64 P1, [%0], %1, 0x989680;\n\t"
            "@P1 bra.uni D_%=;\n\t"
            "bra.uni W_%=;\n\t"
            "D_%=:\n\t}"
            :: "r"(mbar), "r"(parity) : "memory");
    }
}

// ---------------------------------------------------------------------------
// Kernel 2: cluster recurrence. 16 clusters x 8 CTAs; cluster owns 4 batch
// rows; CTA rank owns hidden cols [64r,64r+64); Waa strip pre-packed in
// registers as f32x2 (k,k+1) pairs. Transport: direct st.async scalar remote
// stores from epilogue threads onto per-(source,parity) mbarriers (16,
// distance-2 reuse => race-free). Self-delivery also via st.async, so every
// strip waits uniformly. Red double-buffered => ONE __syncthreads per step.
// Activation block layout [rank][b(4)][k(64)]: ld.shared.v2.b64 feeds FFMA2.
// ---------------------------------------------------------------------------
__global__ void __launch_bounds__(512, 1) __cluster_dims__(8, 1, 1)
recurrence_kernel(const float* __restrict__ Waa, float* __restrict__ A)
{
    extern __shared__ float sm[];
    // sm[0..31]: 16 mbarriers: bar[src][parity] at byte src*16 + par*8
    float* ab  = sm + 32;           // [3 buf][8 rank][4 b][64 k] = 6144 floats
    float* Red = ab + 3 * 2048;     // [2 par][8 ks][4 b][64 hh] = 4096 floats

    const int tid = threadIdx.x;
    uint32_t rank;
    asm("mov.u32 %0, %%cluster_ctarank;" : "=r"(rank));
    const int cl = blockIdx.x >> 3;
    const int b0 = cl * 4;
    const int n0 = (int)rank * 64;
    const int ks = tid >> 6;                 // strip 0..7 (2 warps each)
    const int hh = tid & 63;
    const int k0 = ks * 64;

    const uint32_t mbar0 = (uint32_t)__cvta_generic_to_shared(sm);
    const uint32_t ab_s  = (uint32_t)__cvta_generic_to_shared(ab);

    // Peer SMEM window bases (same layout in every CTA); mbar base = ab - 128B.
    uint32_t peer_ab[8];
#pragma unroll
    for (int r = 0; r < 8; r++) {
        asm("mapa.shared::cluster.u32 %0, %1, %2;"
            : "=r"(peer_ab[r]) : "r"(ab_s), "r"(r));
    }

    // One-time: Waa strip, pre-packed as f32x2 pairs over (k,k+1).
    uint64_t wd[32];
#pragma unroll
    for (int i = 0; i < 16; i++) {
        const float* wp = Waa + (size_t)(k0 + 4 * i) * H_DIM + n0 + hh;
        wd[2 * i]     = pack2(wp[0 * H_DIM], wp[1 * H_DIM]);
        wd[2 * i + 1] = pack2(wp[2 * H_DIM], wp[3 * H_DIM]);
    }

    if (tid < 16) {
        asm volatile("mbarrier.init.shared.b64 [%0], 1;"
                     :: "r"(mbar0 + tid * 8) : "memory");
    }
    for (int i = tid; i < 2048; i += 512) ab[i] = 0.0f;   // a_0 = 0 (buf 0)
    __syncthreads();
    if (tid < 16) {                                        // arm both parities
        asm volatile("mbarrier.arrive.expect_tx.shared.b64 _, [%0], %1;"
                     :: "r"(mbar0 + tid * 8), "r"(1024u) : "memory");
    }
    asm volatile("barrier.cluster.arrive.aligned;" ::: "memory");
    asm volatile("barrier.cluster.wait.aligned;" ::: "memory");

    const int eb = (tid >> 6) & 3;          // epilogue batch (tid<256)
    const int eh = tid & 63;
    const size_t ebase = (size_t)(b0 + eb) * H_DIM + n0 + eh;
    // offset of this thread's value inside a buffer: own rank block, [b][k]
    const uint32_t eoff = rank * 1024u + (uint32_t)(eb * 64 + eh) * 4u;

    for (int t = 0; t < T_DIM; t++) {
        const int cb = t % 3, nb2 = (t + 1) % 3;

        // Prefetch U (d_out holds U[t] here) before the wait.
        float u = 0.0f;
        if (tid < 256) u = __ldcs(&A[(size_t)t * (B_DIM * H_DIM) + ebase]);

        if (t > 0) {
            const uint32_t obj = mbar0 + (uint32_t)(ks * 16 + ((t - 1) & 1) * 8);
            mbar_wait(obj, (uint32_t)(((t - 1) >> 1) & 1));
            if ((tid & 63) == 0) {           // re-arm for reuse at step t+1
                asm volatile("mbarrier.arrive.expect_tx.shared.b64 _, [%0], %1;"
                             :: "r"(obj), "r"(1024u) : "memory");
            }
        }

        // Compute: strip block [b][k]; ld.shared.v2.b64 feeds FFMA2 directly.
        const uint32_t sbase = ab_s + (uint32_t)cb * 8192u + (uint32_t)ks * 1024u;
        uint64_t a0 = 0, a1 = 0, a2 = 0, a3 = 0;
#pragma unroll
        for (int i = 0; i < 16; i++) {
            uint64_t p, q;
            lds_v2b64(sbase +   0u + i * 16u, p, q);
            a0 = fma2(p, wd[2 * i], a0); a0 = fma2(q, wd[2 * i + 1], a0);
            lds_v2b64(sbase + 256u + i * 16u, p, q);
            a1 = fma2(p, wd[2 * i], a1); a1 = fma2(q, wd[2 * i + 1], a1);
            lds_v2b64(sbase + 512u + i * 16u, p, q);
            a2 = fma2(p, wd[2 * i], a2); a2 = fma2(q, wd[2 * i + 1], a2);
            lds_v2b64(sbase + 768u + i * 16u, p, q);
            a3 = fma2(p, wd[2 * i], a3); a3 = fma2(q, wd[2 * i + 1], a3);
        }
        float l0, h0, l1, h1, l2, h2, l3, h3;
        unpack2(a0, l0, h0); unpack2(a1, l1, h1);
        unpack2(a2, l2, h2); unpack2(a3, l3, h3);
        float* Rp = Red + (t & 1) * 2048 + ks * 256 + hh;   // [par][ks][b][hh]
        Rp[  0] = l0 + h0;
        Rp[ 64] = l1 + h1;
        Rp[128] = l2 + h2;
        Rp[192] = l3 + h3;
        __syncthreads();

        if (tid < 256) {
            const float* Rr = Red + (t & 1) * 2048 + eb * 64 + eh;
            float s = u;
#pragma unroll
            for (int w8 = 0; w8 < 8; w8++)
                s += Rr[w8 * 256];
            float val = ftanh(s);
            if (t < T_DIM - 1) {
                // Fan out to all 8 CTAs (incl. self) via st.async; lands on
                // each CTA's bar[rank][t&1].
                const uint32_t doff = (uint32_t)nb2 * 8192u + eoff;
                const uint32_t boff = rank * 16u + (uint32_t)(t & 1) * 8u;
#pragma unroll
                for (int r = 0; r < 8; r++) {
                    const uint32_t da = peer_ab[r] + doff;
                    const uint32_t ma = peer_ab[r] - 128u + boff;
                    asm volatile(
                        "st.async.shared::cluster.mbarrier::complete_tx::bytes.f32 "
                        "[%0], %1, [%2];"
                        :: "r"(da), "f"(val), "r"(ma) : "memory");
                }
            }
            __stcs(&A[(size_t)t * (B_DIM * H_DIM) + ebase], val);
        }
        // No second barrier: Red is parity double-buffered, and all a-buffer
        // reads are mbarrier-gated (self-delivery included).
    }

    // Keep cluster alive until all DSMEM traffic has landed.
    asm volatile("barrier.cluster.arrive.aligned;" ::: "memory");
    asm volatile("barrier.cluster.wait.aligned;" ::: "memory");
}

// ---------------------------------------------------------------------------
extern "C" void kernel_launch(void* const* d_in, const int* in_sizes, int n_in,
                              void* d_out, int out_size)
{
    const float* X   = (const float*)d_in[0];
    const float* Wax = (const float*)d_in[1];
    const float* Waa = (const float*)d_in[2];
    const float* bx  = (const float*)d_in[3];
    const float* ba  = (const float*)d_in[4];
    float* out = (float*)d_out;

    // Actual use ~41KB; request 140KB to pin 1 CTA/SM.
    const int smem_bytes = 140 * 1024;
    cudaFuncSetAttribute(recurrence_kernel,
                         cudaFuncAttributeMaxDynamicSharedMemorySize, smem_bytes);

    dim3 g1(H_DIM / 64, T_DIM / 64, B_DIM);   // (8, 8, 64)
    precompute_kernel<<<g1, 256>>>(X, Wax, bx, ba, out);
    recurrence_kernel<<<128, 512, smem_bytes>>>(Waa, out);
}

// round 9
// speedup vs baseline: 1.1546x; 1.1546x over previous
#include <cuda_runtime.h>
#include <cuda_bf16.h>
#include <cstdint>

#define B_DIM 64
#define H_DIM 512
#define I_DIM 512
#define T_DIM 512

// ---------------------------------------------------------------------------
// Persistent device scratch (static allocation - no runtime allocs)
// ---------------------------------------------------------------------------
__device__ __nv_bfloat16 g_Xt_hi[B_DIM][T_DIM][I_DIM];   // X^T per batch, hi
__device__ __nv_bfloat16 g_Xt_lo[B_DIM][T_DIM][I_DIM];   // X^T per batch, lo
__device__ __nv_bfloat16 g_Wt_hi[H_DIM][I_DIM];          // Wax^T, hi
__device__ __nv_bfloat16 g_Wt_lo[H_DIM][I_DIM];          // Wax^T, lo
__device__ float         g_bias[H_DIM];                  // bx + ba

// ---------------------------------------------------------------------------
// f32x2 helpers (recurrence)
// ---------------------------------------------------------------------------
__device__ __forceinline__ uint64_t pack2(float lo, float hi)
{
    uint64_t r;
    asm("mov.b64 %0, {%1, %2};" : "=l"(r)
        : "r"(__float_as_uint(lo)), "r"(__float_as_uint(hi)));
    return r;
}
__device__ __forceinline__ uint64_t fma2(uint64_t a, uint64_t b, uint64_t c)
{
    uint64_t d;
    asm("fma.rn.f32x2 %0, %1, %2, %3;" : "=l"(d) : "l"(a), "l"(b), "l"(c));
    return d;
}
__device__ __forceinline__ void unpack2(uint64_t v, float& lo, float& hi)
{
    uint32_t l, h;
    asm("mov.b64 {%0, %1}, %2;" : "=r"(l), "=r"(h) : "l"(v));
    lo = __uint_as_float(l); hi = __uint_as_float(h);
}
__device__ __forceinline__ void lds_v2b64(uint32_t addr, uint64_t& p, uint64_t& q)
{
    asm volatile("ld.shared.v2.b64 {%0, %1}, [%2];"
                 : "=l"(p), "=l"(q) : "r"(addr));
}

// tanh = 1 - 2/(e^{2x}+1) via ex2/rcp approx (~1e-6 rel err, saturates).
__device__ __forceinline__ float ftanh(float x)
{
    float e;
    asm("ex2.approx.f32 %0, %1;" : "=f"(e) : "f"(x * 2.885390081777927f));
    float r;
    asm("rcp.approx.f32 %0, %1;" : "=f"(r) : "f"(e + 1.0f));
    return fmaf(-2.0f, r, 1.0f);
}

__device__ __forceinline__ void mbar_wait(uint32_t mbar, uint32_t parity)
{
    uint32_t done;
    asm volatile(
        "{\n\t.reg .pred p;\n\t"
        "mbarrier.try_wait.parity.acquire.cta.shared::cta.b64 p, [%1], %2;\n\t"
        "selp.b32 %0, 1, 0, p;\n\t}"
        : "=r"(done) : "r"(mbar), "r"(parity) : "memory");
    if (!done) {
        asm volatile(
            "{\n\t.reg .pred P1;\n\t"
            "W_%=:\n\t"
            "mbarrier.try_wait.parity.acquire.cta.shared::cta.b64 P1, [%0], %1, 0x989680;\n\t"
            "@P1 bra.uni D_%=;\n\t"
            "bra.uni W_%=;\n\t"
            "D_%=:\n\t}"
            :: "r"(mbar), "r"(parity) : "memory");
    }
}

// ---------------------------------------------------------------------------
// Convert kernels: transpose + bf16 hi/lo split
// ---------------------------------------------------------------------------
__global__ void __launch_bounds__(256)
convert_x_kernel(const float* __restrict__ X)
{
    __shared__ float tile[32][33];
    const int b  = blockIdx.z;
    const int i0 = blockIdx.x * 32;
    const int t0 = blockIdx.y * 32;
    const int lane = threadIdx.x & 31;
    const int r4   = threadIdx.x >> 5;
    const float* Xb = X + (size_t)b * I_DIM * T_DIM;
#pragma unroll
    for (int rr = 0; rr < 4; rr++) {
        int irow = r4 * 4 + rr;
        tile[irow][lane] = Xb[(size_t)(i0 + irow) * T_DIM + t0 + lane];
    }
    __syncthreads();
#pragma unroll
    for (int rr = 0; rr < 4; rr++) {
        int trow = r4 * 4 + rr;
        float v = tile[lane][trow];
        __nv_bfloat16 hi = __float2bfloat16(v);
        float lo = v - __bfloat162float(hi);
        g_Xt_hi[b][t0 + trow][i0 + lane] = hi;
        g_Xt_lo[b][t0 + trow][i0 + lane] = __float2bfloat16(lo);
    }
}

__global__ void __launch_bounds__(256)
convert_w_kernel(const float* __restrict__ Wax)
{
    __shared__ float tile[32][33];
    const int i0 = blockIdx.x * 32;
    const int h0 = blockIdx.y * 32;
    const int lane = threadIdx.x & 31;
    const int r4   = threadIdx.x >> 5;
#pragma unroll
    for (int rr = 0; rr < 4; rr++) {
        int irow = r4 * 4 + rr;
        tile[irow][lane] = Wax[(size_t)(i0 + irow) * H_DIM + h0 + lane];
    }
    __syncthreads();
#pragma unroll
    for (int rr = 0; rr < 4; rr++) {
        int hrow = r4 * 4 + rr;
        float v = tile[lane][hrow];
        __nv_bfloat16 hi = __float2bfloat16(v);
        float lo = v - __bfloat162float(hi);
        g_Wt_hi[h0 + hrow][i0 + lane] = hi;
        g_Wt_lo[h0 + hrow][i0 + lane] = __float2bfloat16(lo);
    }
}

__global__ void __launch_bounds__(512)
bias_kernel(const float* __restrict__ bx, const float* __restrict__ ba)
{
    int h = threadIdx.x;
    g_bias[h] = bx[h] + ba[h];
}

// ---------------------------------------------------------------------------
// mma.sync / ldmatrix helpers (baseline PTX ISA, works on compute_103)
// ---------------------------------------------------------------------------
__device__ __forceinline__ void ldsm4(uint32_t addr, uint32_t* r)
{
    asm volatile("ldmatrix.sync.aligned.m8n8.x4.shared.b16 {%0,%1,%2,%3}, [%4];"
                 : "=r"(r[0]), "=r"(r[1]), "=r"(r[2]), "=r"(r[3]) : "r"(addr));
}
__device__ __forceinline__ void mma16816(float* d, const uint32_t* a,
                                         uint32_t b0, uint32_t b1)
{
    asm volatile(
        "mma.sync.aligned.m16n8k16.row.col.f32.bf16.bf16.f32 "
        "{%0,%1,%2,%3}, {%4,%5,%6,%7}, {%8,%9}, {%0,%1,%2,%3};"
        : "+f"(d[0]), "+f"(d[1]), "+f"(d[2]), "+f"(d[3])
        : "r"(a[0]), "r"(a[1]), "r"(a[2]), "r"(a[3]), "r"(b0), "r"(b1));
}

// ---------------------------------------------------------------------------
// Kernel 1: U = Xt @ Wax^T(+bias) via mma.sync bf16 hi/lo split (3 passes).
// CTA: M=128(t) x N=128(h) x K=512; 8 warps of 64x32; cp.async double-
// buffered K=64 stages; 128B-row XOR swizzle (conflict-free ldmatrix).
// ---------------------------------------------------------------------------
__global__ void __launch_bounds__(256, 1)
u_gemm_kernel(float* __restrict__ U)
{
    extern __shared__ char smem[];
    const uint32_t smem_u = (uint32_t)__cvta_generic_to_shared(smem);
    const int tid  = threadIdx.x;
    const int wid  = tid >> 5;
    const int lane = tid & 31;
    const int h0 = blockIdx.x * 128;
    const int t0 = blockIdx.y * 128;
    const int b  = blockIdx.z;

    float* bias_s = (float*)(smem + 131072);
    if (tid < 128) bias_s[tid] = g_bias[h0 + tid];

    // Stage layout: buf(s) = smem + (s&1)*64KB; tiles 16KB each:
    // [Ahi][Alo][Bhi][Blo]; A rows = t (128 x 64 bf16), B rows = h.
    auto load_stage = [&](int s) {
        const uint32_t buf = smem_u + (uint32_t)(s & 1) * 65536u;
        const int i0 = s * 64;
#pragma unroll
        for (int j = 0; j < 4; j++) {
            int chunk = tid + j * 256;           // 0..1023
            int row = chunk >> 3, kc = chunk & 7;
            uint32_t sw = (uint32_t)(row * 128 + kc * 16);
            sw = sw ^ ((sw >> 3) & 0x70);
            const __nv_bfloat16* ga = &g_Xt_hi[b][t0 + row][i0 + kc * 8];
            const __nv_bfloat16* gb = &g_Xt_lo[b][t0 + row][i0 + kc * 8];
            const __nv_bfloat16* gc = &g_Wt_hi[h0 + row][i0 + kc * 8];
            const __nv_bfloat16* gd = &g_Wt_lo[h0 + row][i0 + kc * 8];
            asm volatile("cp.async.cg.shared.global [%0], [%1], 16;"
                         :: "r"(buf + sw), "l"(ga) : "memory");
            asm volatile("cp.async.cg.shared.global [%0], [%1], 16;"
                         :: "r"(buf + 16384u + sw), "l"(gb) : "memory");
            asm volatile("cp.async.cg.shared.global [%0], [%1], 16;"
                         :: "r"(buf + 32768u + sw), "l"(gc) : "memory");
            asm volatile("cp.async.cg.shared.global [%0], [%1], 16;"
                         :: "r"(buf + 49152u + sw), "l"(gd) : "memory");
        }
        asm volatile("cp.async.commit_group;" ::: "memory");
    };

    // Warp tile: m_off = (wid&1)*64 (t), n_off = (wid>>1)*32 (h).
    const int m_off = (wid & 1) * 64;
    const int n_off = (wid >> 1) * 32;

    // Per-lane ldmatrix address components (swizzle mask = (row&7)*16).
    const uint32_t aRowB = (uint32_t)(m_off + (lane & 15)) * 128u;
    const uint32_t aK8   = (uint32_t)(lane >> 4) * 16u;       // byte col of k-half
    const uint32_t xmA   = (uint32_t)(lane & 7) * 16u;
    const int      brow  = (lane & 7) + ((lane >> 1) & 8);    // +8 for lanes>=16
    const uint32_t bRowB = (uint32_t)(n_off + brow) * 128u;
    const uint32_t bK8   = (uint32_t)(lane & 8) * 2u;         // 0 or 16 bytes
    const uint32_t xmB   = (uint32_t)(lane & 7) * 16u;

    float acc[4][4][4];
#pragma unroll
    for (int i = 0; i < 4; i++)
#pragma unroll
        for (int j = 0; j < 4; j++)
#pragma unroll
            for (int k = 0; k < 4; k++) acc[i][j][k] = 0.0f;

    load_stage(0);
    for (int s = 0; s < 8; s++) {
        if (s < 7) {
            load_stage(s + 1);
            asm volatile("cp.async.wait_group 1;" ::: "memory");
        } else {
            asm volatile("cp.async.wait_group 0;" ::: "memory");
        }
        __syncthreads();

        const uint32_t buf = smem_u + (uint32_t)(s & 1) * 65536u;
#pragma unroll
        for (int k16 = 0; k16 < 4; k16++) {
            const uint32_t colA = ((uint32_t)(k16 * 32) + aK8) ^ xmA;
            const uint32_t colB = ((uint32_t)(k16 * 32) + bK8) ^ xmB;
            uint32_t Ah[4][4], Al[4][4], Bh[2][4], Bl[2][4];
#pragma unroll
            for (int fm = 0; fm < 4; fm++) {
                const uint32_t ad = buf + aRowB + (uint32_t)fm * 2048u + colA;
                ldsm4(ad, Ah[fm]);
                ldsm4(ad + 16384u, Al[fm]);
            }
#pragma unroll
            for (int fn2 = 0; fn2 < 2; fn2++) {
                const uint32_t bd = buf + 32768u + bRowB + (uint32_t)fn2 * 2048u + colB;
                ldsm4(bd, Bh[fn2]);
                ldsm4(bd + 16384u, Bl[fn2]);
            }
#pragma unroll
            for (int fm = 0; fm < 4; fm++) {
#pragma unroll
                for (int fn = 0; fn < 4; fn++) {
                    const int g = fn >> 1, o = (fn & 1) * 2;
                    mma16816(acc[fm][fn], Ah[fm], Bh[g][o], Bh[g][o + 1]);
                    mma16816(acc[fm][fn], Ah[fm], Bl[g][o], Bl[g][o + 1]);
                    mma16816(acc[fm][fn], Al[fm], Bh[g][o], Bh[g][o + 1]);
                }
            }
        }
        __syncthreads();   // protect buffer reuse by loads of stage s+2
    }

    // Epilogue: d0,d1 -> row lane>>2, cols 2*(lane&3)+{0,1}; d2,d3 -> row+8.
    const int row_l = lane >> 2;
    const int col_l = (lane & 3) * 2;
#pragma unroll
    for (int fm = 0; fm < 4; fm++) {
#pragma unroll
        for (int fn = 0; fn < 4; fn++) {
            const int cl = n_off + fn * 8 + col_l;
            const float bi0 = bias_s[cl], bi1 = bias_s[cl + 1];
            const int r0 = t0 + m_off + fm * 16 + row_l;
            float* up0 = U + (size_t)r0 * (B_DIM * H_DIM) + (size_t)b * H_DIM + h0 + cl;
            float2 v0 = make_float2(acc[fm][fn][0] + bi0, acc[fm][fn][1] + bi1);
            *(float2*)up0 = v0;
            float* up1 = up0 + 8 * (B_DIM * H_DIM);
            float2 v1 = make_float2(acc[fm][fn][2] + bi0, acc[fm][fn][3] + bi1);
            *(float2*)up1 = v1;
        }
    }
}

// ---------------------------------------------------------------------------
// Kernel 2: cluster recurrence (unchanged from R7 - proven).
// ---------------------------------------------------------------------------
__global__ void __launch_bounds__(512, 1) __cluster_dims__(8, 1, 1)
recurrence_kernel(const float* __restrict__ Waa, float* __restrict__ A)
{
    extern __shared__ float sm[];
    float* ab  = sm + 32;           // [3 buf][8 rank][4 b][64 k] = 6144 floats
    float* Red = ab + 3 * 2048;     // [2 par][8 ks][4 b][64 hh] = 4096 floats

    const int tid = threadIdx.x;
    uint32_t rank;
    asm("mov.u32 %0, %%cluster_ctarank;" : "=r"(rank));
    const int cl = blockIdx.x >> 3;
    const int b0 = cl * 4;
    const int n0 = (int)rank * 64;
    const int ks = tid >> 6;
    const int hh = tid & 63;
    const int k0 = ks * 64;

    const uint32_t mbar0 = (uint32_t)__cvta_generic_to_shared(sm);
    const uint32_t ab_s  = (uint32_t)__cvta_generic_to_shared(ab);

    uint32_t peer_ab[8];
#pragma unroll
    for (int r = 0; r < 8; r++) {
        asm("mapa.shared::cluster.u32 %0, %1, %2;"
            : "=r"(peer_ab[r]) : "r"(ab_s), "r"(r));
    }

    uint64_t wd[32];
#pragma unroll
    for (int i = 0; i < 16; i++) {
        const float* wp = Waa + (size_t)(k0 + 4 * i) * H_DIM + n0 + hh;
        wd[2 * i]     = pack2(wp[0 * H_DIM], wp[1 * H_DIM]);
        wd[2 * i + 1] = pack2(wp[2 * H_DIM], wp[3 * H_DIM]);
    }

    if (tid < 16) {
        asm volatile("mbarrier.init.shared.b64 [%0], 1;"
                     :: "r"(mbar0 + tid * 8) : "memory");
    }
    for (int i = tid; i < 2048; i += 512) ab[i] = 0.0f;
    __syncthreads();
    if (tid < 16) {
        asm volatile("mbarrier.arrive.expect_tx.shared.b64 _, [%0], %1;"
                     :: "r"(mbar0 + tid * 8), "r"(1024u) : "memory");
    }
    asm volatile("barrier.cluster.arrive.aligned;" ::: "memory");
    asm volatile("barrier.cluster.wait.aligned;" ::: "memory");

    const int eb = (tid >> 6) & 3;
    const int eh = tid & 63;
    const size_t ebase = (size_t)(b0 + eb) * H_DIM + n0 + eh;
    const uint32_t eoff = rank * 1024u + (uint32_t)(eb * 64 + eh) * 4u;

    for (int t = 0; t < T_DIM; t++) {
        const int cb = t % 3, nb2 = (t + 1) % 3;

        float u = 0.0f;
        if (tid < 256) u = __ldcs(&A[(size_t)t * (B_DIM * H_DIM) + ebase]);

        if (t > 0) {
            const uint32_t obj = mbar0 + (uint32_t)(ks * 16 + ((t - 1) & 1) * 8);
            mbar_wait(obj, (uint32_t)(((t - 1) >> 1) & 1));
            if ((tid & 63) == 0) {
                asm volatile("mbarrier.arrive.expect_tx.shared.b64 _, [%0], %1;"
                             :: "r"(obj), "r"(1024u) : "memory");
            }
        }

        const uint32_t sbase = ab_s + (uint32_t)cb * 8192u + (uint32_t)ks * 1024u;
        uint64_t a0 = 0, a1 = 0, a2 = 0, a3 = 0;
#pragma unroll
        for (int i = 0; i < 16; i++) {
            uint64_t p, q;
            lds_v2b64(sbase +   0u + i * 16u, p, q);
            a0 = fma2(p, wd[2 * i], a0); a0 = fma2(q, wd[2 * i + 1], a0);
            lds_v2b64(sbase + 256u + i * 16u, p, q);
            a1 = fma2(p, wd[2 * i], a1); a1 = fma2(q, wd[2 * i + 1], a1);
            lds_v2b64(sbase + 512u + i * 16u, p, q);
            a2 = fma2(p, wd[2 * i], a2); a2 = fma2(q, wd[2 * i + 1], a2);
            lds_v2b64(sbase + 768u + i * 16u, p, q);
            a3 = fma2(p, wd[2 * i], a3); a3 = fma2(q, wd[2 * i + 1], a3);
        }
        float l0, h0, l1, h1, l2, h2, l3, h3;
        unpack2(a0, l0, h0); unpack2(a1, l1, h1);
        unpack2(a2, l2, h2); unpack2(a3, l3, h3);
        float* Rp = Red + (t & 1) * 2048 + ks * 256 + hh;
        Rp[  0] = l0 + h0;
        Rp[ 64] = l1 + h1;
        Rp[128] = l2 + h2;
        Rp[192] = l3 + h3;
        __syncthreads();

        if (tid < 256) {
            const float* Rr = Red + (t & 1) * 2048 + eb * 64 + eh;
            float s = u;
#pragma unroll
            for (int w8 = 0; w8 < 8; w8++)
                s += Rr[w8 * 256];
            float val = ftanh(s);
            if (t < T_DIM - 1) {
                const uint32_t doff = (uint32_t)nb2 * 8192u + eoff;
                const uint32_t boff = rank * 16u + (uint32_t)(t & 1) * 8u;
#pragma unroll
                for (int r = 0; r < 8; r++) {
                    const uint32_t da = peer_ab[r] + doff;
                    const uint32_t ma = peer_ab[r] - 128u + boff;
                    asm volatile(
                        "st.async.shared::cluster.mbarrier::complete_tx::bytes.f32 "
                        "[%0], %1, [%2];"
                        :: "r"(da), "f"(val), "r"(ma) : "memory");
                }
            }
            __stcs(&A[(size_t)t * (B_DIM * H_DIM) + ebase], val);
        }
    }

    asm volatile("barrier.cluster.arrive.aligned;" ::: "memory");
    asm volatile("barrier.cluster.wait.aligned;" ::: "memory");
}

// ---------------------------------------------------------------------------
extern "C" void kernel_launch(void* const* d_in, const int* in_sizes, int n_in,
                              void* d_out, int out_size)
{
    const float* X   = (const float*)d_in[0];
    const float* Wax = (const float*)d_in[1];
    const float* Waa = (const float*)d_in[2];
    const float* bx  = (const float*)d_in[3];
    const float* ba  = (const float*)d_in[4];
    float* out = (float*)d_out;

    const int gemm_smem = 132 * 1024;
    cudaFuncSetAttribute(u_gemm_kernel,
                         cudaFuncAttributeMaxDynamicSharedMemorySize, gemm_smem);
    const int rec_smem = 140 * 1024;   // pin 1 CTA/SM
    cudaFuncSetAttribute(recurrence_kernel,
                         cudaFuncAttributeMaxDynamicSharedMemorySize, rec_smem);

    convert_x_kernel<<<dim3(16, 16, 64), 256>>>(X);
    convert_w_kernel<<<dim3(16, 16), 256>>>(Wax);
    bias_kernel<<<1, 512>>>(bx, ba);
    u_gemm_kernel<<<dim3(4, 4, 64), 256, gemm_smem>>>(out);
    recurrence_kernel<<<128, 512, rec_smem>>>(Waa, out);
}